// round 1
// baseline (speedup 1.0000x reference)
#include <cuda_runtime.h>
#include <mma.h>

using namespace nvcuda;

namespace {

constexpr int Bsz = 128;   // batch
constexpr int L1  = 1024;  // ctx rows
constexpr int L2n = 128;   // asp rows (output cols)
constexpr int H2  = 600;   // K
constexpr int KT  = 40;    // K tile (600 = 15 * 40)
constexpr int NIT = H2 / KT;
constexpr int LDA = KT + 4;    // 44 floats; 176B rows -> float4-aligned
constexpr int LDC = 132;       // 128 + 4 pad; 528B rows -> float4-aligned

struct Smem {
    union {
        float bufs[2][2][128 * LDA];   // [stage][0=A(ctx raw) 1=B(asp*w3)]
        float C[128 * LDC];            // epilogue staging (reuses buffers)
    };
    float w[3 * H2];        // w1 | w2 | w3
    float sasp[128];
    float sctx_part[256];
    float sctx[128];
};

__global__ void __launch_bounds__(256, 1)
align_kernel(const float* __restrict__ ctx, const float* __restrict__ asp,
             const float* __restrict__ wu, float* __restrict__ out)
{
    extern __shared__ char smraw[];
    Smem& s = *reinterpret_cast<Smem*>(smraw);

    const int tid = threadIdx.x;
    const int mt  = blockIdx.x;   // 0..7
    const int b   = blockIdx.y;   // 0..127

    const float* ctxb = ctx + ((size_t)b * L1 + (size_t)mt * 128) * H2;
    const float* aspb = asp + (size_t)b * L2n * H2;

    // Load w1,w2,w3 to smem
    for (int i = tid; i < 3 * H2; i += 256) s.w[i] = wu[i];
    __syncthreads();

    // s_asp[j] = asp[b,j,:] . w2   (8 warps x 16 rows, coalesced, warp-reduced)
    {
        const int warp = tid >> 5, lane = tid & 31;
        for (int rr = 0; rr < 16; rr++) {
            const int j = warp * 16 + rr;
            float acc = 0.f;
            for (int k = lane; k < H2; k += 32)
                acc += aspb[(size_t)j * H2 + k] * s.w[H2 + k];
            #pragma unroll
            for (int o = 16; o; o >>= 1) acc += __shfl_xor_sync(0xffffffffu, acc, o);
            if (lane == 0) s.sasp[j] = acc;
        }
    }

    // Warp tiling: 4 (M) x 2 (N) warps; each warp 32x64 = 2x4 wmma tiles
    const int warp = tid >> 5;
    const int wm = warp & 3;
    const int wn = warp >> 2;
    const int m0w = wm * 32;
    const int n0w = wn * 64;

    wmma::fragment<wmma::accumulator, 16, 16, 8, float> cf[2][4];
    #pragma unroll
    for (int im = 0; im < 2; im++)
        #pragma unroll
        for (int in = 0; in < 4; in++)
            wmma::fill_fragment(cf[im][in], 0.f);

    float4 ra[5], rb[5];

    // ---- Prologue: load + store tile 0 ----
    #pragma unroll
    for (int i = 0; i < 5; i++) {
        const int f = tid + i * 256, r = f / 10, c4 = f % 10;
        ra[i] = *(const float4*)(ctxb + (size_t)r * H2 + c4 * 4);
        rb[i] = *(const float4*)(aspb + (size_t)r * H2 + c4 * 4);
    }
    #pragma unroll
    for (int i = 0; i < 5; i++) {
        const int f = tid + i * 256, r = f / 10, c4 = f % 10;
        *(float4*)&s.bufs[0][0][r * LDA + c4 * 4] = ra[i];
        float4 v = rb[i];
        const int k = c4 * 4;
        v.x *= s.w[2 * H2 + k + 0];
        v.y *= s.w[2 * H2 + k + 1];
        v.z *= s.w[2 * H2 + k + 2];
        v.w *= s.w[2 * H2 + k + 3];
        *(float4*)&s.bufs[0][1][r * LDA + c4 * 4] = v;
    }
    __syncthreads();

    const int myrow = tid >> 1, myhalf = tid & 1;
    float sctx_acc = 0.f;

    // ---- Mainloop ----
    for (int t = 0; t < NIT; t++) {
        const int p = t & 1;

        // prefetch next K tile gmem -> regs
        if (t + 1 < NIT) {
            const int k0 = (t + 1) * KT;
            #pragma unroll
            for (int i = 0; i < 5; i++) {
                const int f = tid + i * 256, r = f / 10, c4 = f % 10;
                ra[i] = *(const float4*)(ctxb + (size_t)r * H2 + k0 + c4 * 4);
                rb[i] = *(const float4*)(aspb + (size_t)r * H2 + k0 + c4 * 4);
            }
        }

        // compute on buffer p
        const float* Ab = &s.bufs[p][0][0];
        const float* Bb = &s.bufs[p][1][0];
        #pragma unroll
        for (int kk = 0; kk < KT / 8; kk++) {
            wmma::fragment<wmma::matrix_a, 16, 16, 8, wmma::precision::tf32, wmma::row_major> af[2];
            wmma::fragment<wmma::matrix_b, 16, 16, 8, wmma::precision::tf32, wmma::col_major> bf[4];
            #pragma unroll
            for (int im = 0; im < 2; im++) {
                wmma::load_matrix_sync(af[im], Ab + (m0w + 16 * im) * LDA + kk * 8, LDA);
                #pragma unroll
                for (int e = 0; e < af[im].num_elements; e++)
                    af[im].x[e] = wmma::__float_to_tf32(af[im].x[e]);
            }
            #pragma unroll
            for (int in = 0; in < 4; in++) {
                wmma::load_matrix_sync(bf[in], Bb + (n0w + 16 * in) * LDA + kk * 8, LDA);
                #pragma unroll
                for (int e = 0; e < bf[in].num_elements; e++)
                    bf[in].x[e] = wmma::__float_to_tf32(bf[in].x[e]);
            }
            #pragma unroll
            for (int im = 0; im < 2; im++)
                #pragma unroll
                for (int in = 0; in < 4; in++)
                    wmma::mma_sync(cf[im][in], af[im], bf[in], cf[im][in]);
        }

        // fused s_ctx partial: raw ctx in A buffer, dot with w1 (fp32)
        {
            const int k0 = t * KT;
            const float* Ar  = Ab + myrow * LDA + myhalf * 20;
            const float* w1p = &s.w[k0 + myhalf * 20];
            #pragma unroll
            for (int kk = 0; kk < 20; kk++) sctx_acc += Ar[kk] * w1p[kk];
        }

        // store next tile regs -> smem (other buffer), scaling B by w3
        if (t + 1 < NIT) {
            const int k0n = (t + 1) * KT;
            #pragma unroll
            for (int i = 0; i < 5; i++) {
                const int f = tid + i * 256, r = f / 10, c4 = f % 10;
                *(float4*)&s.bufs[p ^ 1][0][r * LDA + c4 * 4] = ra[i];
                float4 v = rb[i];
                const int k = k0n + c4 * 4;
                v.x *= s.w[2 * H2 + k + 0];
                v.y *= s.w[2 * H2 + k + 1];
                v.z *= s.w[2 * H2 + k + 2];
                v.w *= s.w[2 * H2 + k + 3];
                *(float4*)&s.bufs[p ^ 1][1][r * LDA + c4 * 4] = v;
            }
        }
        __syncthreads();
    }

    // ---- Epilogue ----
    s.sctx_part[tid] = sctx_acc;
    __syncthreads();
    if (tid < 128) s.sctx[tid] = s.sctx_part[2 * tid] + s.sctx_part[2 * tid + 1];

    #pragma unroll
    for (int im = 0; im < 2; im++)
        #pragma unroll
        for (int in = 0; in < 4; in++)
            wmma::store_matrix_sync(&s.C[(m0w + 16 * im) * LDC + (n0w + 16 * in)],
                                    cf[im][in], LDC, wmma::mem_row_major);
    __syncthreads();

    float* outb = out + ((size_t)b * L1 + (size_t)mt * 128) * L2n;
    #pragma unroll
    for (int i = 0; i < 16; i++) {
        const int f = tid + i * 256, r = f / 32, c4 = f % 32;
        float4 v = *(float4*)&s.C[r * LDC + c4 * 4];
        const float sc = s.sctx[r];
        v.x += sc + s.sasp[c4 * 4 + 0];
        v.y += sc + s.sasp[c4 * 4 + 1];
        v.z += sc + s.sasp[c4 * 4 + 2];
        v.w += sc + s.sasp[c4 * 4 + 3];
        *(float4*)(outb + (size_t)r * L2n + c4 * 4) = v;
    }
}

} // namespace

extern "C" void kernel_launch(void* const* d_in, const int* in_sizes, int n_in,
                              void* d_out, int out_size)
{
    const float* ctx = nullptr;
    const float* asp = nullptr;
    const float* wu  = nullptr;
    for (int i = 0; i < n_in; i++) {
        const long sz = (long)in_sizes[i];
        if (sz == (long)Bsz * L1 * H2)       ctx = (const float*)d_in[i];
        else if (sz == (long)Bsz * L2n * H2) asp = (const float*)d_in[i];
        else if (sz == 3 * H2)               wu  = (const float*)d_in[i];
    }

    cudaFuncSetAttribute(align_kernel, cudaFuncAttributeMaxDynamicSharedMemorySize,
                         (int)sizeof(Smem));

    dim3 grid(L1 / 128, Bsz);
    align_kernel<<<grid, 256, sizeof(Smem)>>>(ctx, asp, wu, (float*)d_out);
}

// round 4
// speedup vs baseline: 2.4065x; 2.4065x over previous
#include <cuda_runtime.h>
#include <cstdint>

namespace {

constexpr int Bsz  = 128;
constexpr int L1   = 1024;
constexpr int L2n  = 128;
constexpr int H2   = 600;
constexpr int KPAD = 608;           // 19 * 32
constexpr int KT   = 32;            // K per stage tile
constexpr int T    = KPAD / KT;     // 19
constexpr int S    = 4;             // pipeline stages
constexpr int PRE  = 3;

constexpr int STRD = 36;            // smem row stride in floats (conflict-free)
constexpr int A_ROWS = 128, B_ROWS = 128;
constexpr int STAGE_FLOATS = (A_ROWS + B_ROWS) * STRD;   // 9216
constexpr int STAGE_BYTES  = STAGE_FLOATS * 4;           // 36864
constexpr int SM_SASP  = 0;                              // 128 floats
constexpr int SM_STAGE = 512;                            // byte offset
constexpr int SMEM_TOTAL = SM_STAGE + S * STAGE_BYTES;   // 147968

__device__ float g_bscaled[(size_t)Bsz * L2n * KPAD];    // ~39.8MB scratch
__device__ float g_sasp[Bsz * L2n];

__device__ __forceinline__ uint32_t cvta_s(const void* p) {
    uint32_t a;
    asm("{ .reg .u64 t; cvta.to.shared.u64 t, %1; cvt.u32.u64 %0, t; }"
        : "=r"(a) : "l"(p));
    return a;
}
__device__ __forceinline__ void cp16(uint32_t d, const void* s) {
    asm volatile("cp.async.cg.shared.global [%0], [%1], 16;" :: "r"(d), "l"(s));
}
__device__ __forceinline__ void cp16z(uint32_t d, const void* s) {
    asm volatile("cp.async.cg.shared.global [%0], [%1], 16, 0;" :: "r"(d), "l"(s));
}
#define CPCOMMIT() asm volatile("cp.async.commit_group;" ::: "memory")
#define CPWAIT(n)  asm volatile("cp.async.wait_group %0;" :: "n"(n) : "memory")

__device__ __forceinline__ void mma8(float& d0, float& d1, float& d2, float& d3,
                                     uint32_t a0, uint32_t a1, uint32_t a2, uint32_t a3,
                                     uint32_t b0, uint32_t b1) {
    asm volatile(
        "mma.sync.aligned.m16n8k8.row.col.f32.tf32.tf32.f32 "
        "{%0,%1,%2,%3}, {%4,%5,%6,%7}, {%8,%9}, {%0,%1,%2,%3};"
        : "+f"(d0), "+f"(d1), "+f"(d2), "+f"(d3)
        : "r"(a0), "r"(a1), "r"(a2), "r"(a3), "r"(b0), "r"(b1));
}

// ---- pre-pass: B' = rn_tf32(w3*asp + w1) [K padded to 608], s_asp = asp.w2 ----
__global__ void __launch_bounds__(256) prep_kernel(const float* __restrict__ asp,
                                                   const float* __restrict__ wu) {
    const int gwarp = (blockIdx.x * blockDim.x + threadIdx.x) >> 5;
    const int lane  = threadIdx.x & 31;
    if (gwarp >= Bsz * L2n) return;
    const float* row = asp + (size_t)gwarp * H2;
    float* orow = g_bscaled + (size_t)gwarp * KPAD;
    float acc = 0.f;
    for (int k = lane; k < H2; k += 32) {
        const float a = row[k];
        float v = fmaf(a, __ldg(wu + 2 * H2 + k), __ldg(wu + k));
        asm("cvt.rna.tf32.f32 %0, %1;" : "=f"(v) : "f"(v));
        orow[k] = v;
        acc += a * __ldg(wu + H2 + k);
    }
    if (lane >= 24) orow[H2 + lane - 24] = 0.f;  // pad 600..607
    #pragma unroll
    for (int o = 16; o; o >>= 1) acc += __shfl_xor_sync(0xffffffffu, acc, o);
    if (lane == 0) g_sasp[gwarp] = acc;
}

// ---- main GEMM: mma.sync tf32, CTA 128x128, 16 warps, cp.async 4-stage ----
__global__ void __launch_bounds__(512, 1)
gemm_kernel(const float* __restrict__ ctx, float* __restrict__ out) {
    extern __shared__ float sm[];
    const uint32_t sb = cvta_s(sm);
    const int tid  = threadIdx.x;
    const int lane = tid & 31;
    const int wid  = tid >> 5;
    const int wm = wid & 3, wn = wid >> 2;
    const int m0 = wm * 32, n0 = wn * 32;
    const int g  = lane >> 2;        // groupID
    const int tg = lane & 3;         // threadID_in_group
    const int mt = blockIdx.x, b = blockIdx.y;

    const float* actx = ctx + (size_t)(b * L1 + mt * 128) * H2;
    const float* absc = g_bscaled + (size_t)b * L2n * KPAD;

    if (tid < 128) sm[SM_SASP + tid] = g_sasp[b * L2n + tid];

    float acc[2][4][4];
    #pragma unroll
    for (int i = 0; i < 2; i++)
        #pragma unroll
        for (int j = 0; j < 4; j++)
            #pragma unroll
            for (int q = 0; q < 4; q++) acc[i][j][q] = 0.f;

    // stage filler: 2048 16B chunks, 4 per thread
    auto issue = [&](int t) {
        const int k0 = t * KT;
        const uint32_t st = sb + SM_STAGE + (t % S) * STAGE_BYTES;
        #pragma unroll
        for (int i = 0; i < 4; i++) {
            const int f = tid + i * 512;
            const int r = f >> 3, u = f & 7;
            if (r < 128) {
                const uint32_t d = st + (uint32_t)(r * STRD * 4 + u * 16);
                if (k0 + u * 4 < H2) cp16(d, actx + (size_t)r * H2 + k0 + u * 4);
                else                 cp16z(d, actx);
            } else {
                const int rb = r - 128;
                const uint32_t d = st + (uint32_t)((A_ROWS + rb) * STRD * 4 + u * 16);
                cp16(d, absc + (size_t)rb * KPAD + k0 + u * 4);
            }
        }
    };

    #pragma unroll
    for (int t = 0; t < PRE; t++) { issue(t); CPCOMMIT(); }

    for (int t = 0; t < T; t++) {
        CPWAIT(PRE - 1);
        __syncthreads();

        const uint32_t stg = sb + SM_STAGE + (t % S) * STAGE_BYTES;
        // per-thread fragment base addresses (bytes)
        const uint32_t Abase = stg + (uint32_t)(((m0 + g) * STRD + tg) * 4);
        const uint32_t Bbase = stg + (uint32_t)(((A_ROWS + n0 + g) * STRD + tg) * 4);

        #pragma unroll
        for (int kk = 0; kk < 4; kk++) {
            const uint32_t ko = kk * 8 * 4;
            uint32_t a[2][4], bfr[4][2];
            #pragma unroll
            for (int im = 0; im < 2; im++) {
                const uint32_t ab = Abase + im * 16 * STRD * 4 + ko;
                asm volatile("ld.shared.b32 %0, [%1];"       : "=r"(a[im][0]) : "r"(ab));
                asm volatile("ld.shared.b32 %0, [%1+%2];"    : "=r"(a[im][1]) : "r"(ab), "n"(8 * STRD * 4));
                asm volatile("ld.shared.b32 %0, [%1+16];"    : "=r"(a[im][2]) : "r"(ab));
                asm volatile("ld.shared.b32 %0, [%1+%2];"    : "=r"(a[im][3]) : "r"(ab), "n"(8 * STRD * 4 + 16));
            }
            #pragma unroll
            for (int in = 0; in < 4; in++) {
                const uint32_t bb = Bbase + in * 8 * STRD * 4 + ko;
                asm volatile("ld.shared.b32 %0, [%1];"    : "=r"(bfr[in][0]) : "r"(bb));
                asm volatile("ld.shared.b32 %0, [%1+16];" : "=r"(bfr[in][1]) : "r"(bb));
            }
            #pragma unroll
            for (int im = 0; im < 2; im++)
                #pragma unroll
                for (int in = 0; in < 4; in++)
                    mma8(acc[im][in][0], acc[im][in][1], acc[im][in][2], acc[im][in][3],
                         a[im][0], a[im][1], a[im][2], a[im][3],
                         bfr[in][0], bfr[in][1]);
        }

        if (t + PRE < T) issue(t + PRE);
        CPCOMMIT();
    }

    // ---- epilogue: add s_asp, store float2 per fragment half ----
    float* outb = out + (size_t)(b * L1 + mt * 128) * L2n;
    #pragma unroll
    for (int im = 0; im < 2; im++) {
        const int r0 = m0 + im * 16 + g;
        #pragma unroll
        for (int in = 0; in < 4; in++) {
            const int c = n0 + in * 8 + 2 * tg;
            const float s0 = sm[SM_SASP + c], s1 = sm[SM_SASP + c + 1];
            float2 v0 = { acc[im][in][0] + s0, acc[im][in][1] + s1 };
            float2 v1 = { acc[im][in][2] + s0, acc[im][in][3] + s1 };
            *(float2*)(outb + (size_t)r0 * L2n + c)       = v0;
            *(float2*)(outb + (size_t)(r0 + 8) * L2n + c) = v1;
        }
    }
}

}  // namespace

extern "C" void kernel_launch(void* const* d_in, const int* in_sizes, int n_in,
                              void* d_out, int out_size) {
    const float* ctx = nullptr;
    const float* asp = nullptr;
    const float* wu  = nullptr;
    for (int i = 0; i < n_in; i++) {
        const long sz = (long)in_sizes[i];
        if (sz == (long)Bsz * L1 * H2)       ctx = (const float*)d_in[i];
        else if (sz == (long)Bsz * L2n * H2) asp = (const float*)d_in[i];
        else if (sz == 3 * H2)               wu  = (const float*)d_in[i];
    }

    prep_kernel<<<(Bsz * L2n) / 8, 256>>>(asp, wu);

    cudaFuncSetAttribute(gemm_kernel, cudaFuncAttributeMaxDynamicSharedMemorySize,
                         SMEM_TOTAL);
    dim3 grid(L1 / 128, Bsz);
    gemm_kernel<<<grid, 512, SMEM_TOTAL>>>(ctx, (float*)d_out);
}

// round 7
// speedup vs baseline: 3.2184x; 1.3374x over previous
#include <cuda_runtime.h>
#include <cstdint>

namespace {

constexpr int Bsz  = 128;
constexpr int L1   = 1024;
constexpr int L2n  = 128;
constexpr int H2   = 600;
constexpr int KPAD = 608;           // 19 * 32
constexpr int KT   = 32;            // K per stage tile
constexpr int T    = KPAD / KT;     // 19
constexpr int S    = 3;             // pipeline stages
constexpr int PRE  = 2;

constexpr int STRD = 36;            // smem row stride (floats); 144B rows
constexpr int A_ROWS = 128, B_ROWS = 128;
constexpr int STAGE_BYTES = (A_ROWS + B_ROWS) * STRD * 4;    // 36864
constexpr int SM_SASP_B   = 0;                               // 128 floats (bytes 0..511)
constexpr int SM_STAGE_B  = 512;                             // byte offset of stage 0
constexpr int SMEM_TOTAL  = SM_STAGE_B + S * STAGE_BYTES;    // 111104 (x2 fits /SM)

__device__ float g_bscaled[(size_t)Bsz * L2n * KPAD];        // ~39.8MB scratch
__device__ float g_sasp[Bsz * L2n];

__device__ __forceinline__ uint32_t cvta_s(const void* p) {
    uint32_t a;
    asm("{ .reg .u64 t; cvta.to.shared.u64 t, %1; cvt.u32.u64 %0, t; }"
        : "=r"(a) : "l"(p));
    return a;
}
__device__ __forceinline__ void cp16(uint32_t d, const void* s) {
    asm volatile("cp.async.cg.shared.global [%0], [%1], 16;" :: "r"(d), "l"(s));
}
__device__ __forceinline__ void cp16z(uint32_t d, const void* s) {
    asm volatile("cp.async.cg.shared.global [%0], [%1], 16, 0;" :: "r"(d), "l"(s));
}
#define CPCOMMIT() asm volatile("cp.async.commit_group;" ::: "memory")
#define CPWAIT(n)  asm volatile("cp.async.wait_group %0;" :: "n"(n) : "memory")

__device__ __forceinline__ void ldsm4(uint32_t& r0, uint32_t& r1, uint32_t& r2,
                                      uint32_t& r3, uint32_t a) {
    asm volatile("ldmatrix.sync.aligned.m8n8.x4.shared.b16 {%0,%1,%2,%3}, [%4];"
                 : "=r"(r0), "=r"(r1), "=r"(r2), "=r"(r3) : "r"(a));
}
__device__ __forceinline__ void mma8(float& d0, float& d1, float& d2, float& d3,
                                     uint32_t a0, uint32_t a1, uint32_t a2, uint32_t a3,
                                     uint32_t b0, uint32_t b1) {
    asm volatile(
        "mma.sync.aligned.m16n8k8.row.col.f32.tf32.tf32.f32 "
        "{%0,%1,%2,%3}, {%4,%5,%6,%7}, {%8,%9}, {%0,%1,%2,%3};"
        : "+f"(d0), "+f"(d1), "+f"(d2), "+f"(d3)
        : "r"(a0), "r"(a1), "r"(a2), "r"(a3), "r"(b0), "r"(b1));
}

// ---- pre-pass: B' = rn_tf32(w3*asp + w1) [K padded to 608], s_asp = asp.w2 ----
__global__ void __launch_bounds__(256) prep_kernel(const float* __restrict__ asp,
                                                   const float* __restrict__ wu) {
    const int gwarp = (blockIdx.x * blockDim.x + threadIdx.x) >> 5;
    const int lane  = threadIdx.x & 31;
    if (gwarp >= Bsz * L2n) return;
    const float* row = asp + (size_t)gwarp * H2;
    float* orow = g_bscaled + (size_t)gwarp * KPAD;
    float acc = 0.f;
    for (int k = lane; k < H2; k += 32) {
        const float a = row[k];
        float v = fmaf(a, __ldg(wu + 2 * H2 + k), __ldg(wu + k));
        asm("cvt.rna.tf32.f32 %0, %1;" : "=f"(v) : "f"(v));
        orow[k] = v;
        acc += a * __ldg(wu + H2 + k);
    }
    if (lane >= 24) orow[H2 + lane - 24] = 0.f;  // pad 600..607
    #pragma unroll
    for (int o = 16; o; o >>= 1) acc += __shfl_xor_sync(0xffffffffu, acc, o);
    if (lane == 0) g_sasp[gwarp] = acc;
}

// ---- main GEMM: mma.sync tf32, CTA 128x128, 8 warps (64x32 tiles), 2 CTA/SM ----
__global__ void __launch_bounds__(256, 2)
gemm_kernel(const float* __restrict__ ctx, float* __restrict__ out) {
    extern __shared__ float sm[];
    const uint32_t sb = cvta_s(sm);
    const int tid  = threadIdx.x;
    const int lane = tid & 31;
    const int wid  = tid >> 5;
    const int wm = wid >> 2, wn = wid & 3;     // 2 x 4 warp grid
    const int m0 = wm * 64, n0 = wn * 32;
    const int g  = lane >> 2;
    const int tg = lane & 3;
    const int mt = blockIdx.x, b = blockIdx.y;

    const float* actx = ctx + (size_t)(b * L1 + mt * 128) * H2;
    const float* absc = g_bscaled + (size_t)b * L2n * KPAD;

    if (tid < 128) sm[tid] = g_sasp[b * L2n + tid];

    float acc[4][4][4];
    #pragma unroll
    for (int i = 0; i < 4; i++)
        #pragma unroll
        for (int j = 0; j < 4; j++)
            #pragma unroll
            for (int q = 0; q < 4; q++) acc[i][j][q] = 0.f;

    // ldmatrix per-lane address offsets (bytes, within a stage)
    // A tiles: lanes 0-7 rows 0-7 @k0, 8-15 rows 8-15 @k0, 16-23 rows 0-7 @k0+4,
    //          24-31 rows 8-15 @k0+4
    const uint32_t aoff = (uint32_t)((m0 + (lane & 15)) * STRD * 4 + ((lane >> 4) << 4));
    // B pair (2 n-tiles): lanes 0-7 n0-7@k0, 8-15 n0-7@k0+4, 16-23 n8-15@k0,
    //          24-31 n8-15@k0+4
    const uint32_t boff = (uint32_t)((A_ROWS + n0 + ((lane >> 4) << 3) + (lane & 7)) * STRD * 4
                                     + (((lane >> 3) & 1) << 4));

    // stage filler: 2048 16B chunks, 8 per thread
    auto issue = [&](int t) {
        const int k0 = t * KT;
        const uint32_t st = sb + SM_STAGE_B + (t % S) * STAGE_BYTES;
        #pragma unroll
        for (int i = 0; i < 8; i++) {
            const int f = tid + i * 256;
            const int r = f >> 3, u = f & 7;
            if (r < 128) {
                const uint32_t d = st + (uint32_t)(r * STRD * 4 + u * 16);
                if (k0 + u * 4 < H2) cp16(d, actx + (size_t)r * H2 + k0 + u * 4);
                else                 cp16z(d, actx);
            } else {
                const int rb = r - 128;
                const uint32_t d = st + (uint32_t)((A_ROWS + rb) * STRD * 4 + u * 16);
                cp16(d, absc + (size_t)rb * KPAD + k0 + u * 4);
            }
        }
    };

    #pragma unroll
    for (int t = 0; t < PRE; t++) { issue(t); CPCOMMIT(); }

    for (int t = 0; t < T; t++) {
        CPWAIT(PRE - 1);
        __syncthreads();

        const uint32_t stg = sb + SM_STAGE_B + (t % S) * STAGE_BYTES;
        const uint32_t aB = stg + aoff;
        const uint32_t bB = stg + boff;

        #pragma unroll
        for (int kk = 0; kk < 4; kk++) {
            uint32_t af[4][4], bf[4][2];
            #pragma unroll
            for (int im = 0; im < 4; im++)
                ldsm4(af[im][0], af[im][1], af[im][2], af[im][3],
                      aB + im * 16 * STRD * 4 + kk * 32);
            #pragma unroll
            for (int p = 0; p < 2; p++)
                ldsm4(bf[2 * p][0], bf[2 * p][1], bf[2 * p + 1][0], bf[2 * p + 1][1],
                      bB + p * 16 * STRD * 4 + kk * 32);
            #pragma unroll
            for (int im = 0; im < 4; im++)
                #pragma unroll
                for (int in = 0; in < 4; in++)
                    mma8(acc[im][in][0], acc[im][in][1], acc[im][in][2], acc[im][in][3],
                         af[im][0], af[im][1], af[im][2], af[im][3],
                         bf[in][0], bf[in][1]);
        }

        if (t + PRE < T) issue(t + PRE);
        CPCOMMIT();
    }

    // ---- epilogue: add s_asp, store float2 per fragment half ----
    float* outb = out + (size_t)(b * L1 + mt * 128) * L2n;
    #pragma unroll
    for (int im = 0; im < 4; im++) {
        const int r0 = m0 + im * 16 + g;
        #pragma unroll
        for (int in = 0; in < 4; in++) {
            const int c = n0 + in * 8 + 2 * tg;
            const float s0 = sm[c], s1 = sm[c + 1];
            float2 v0 = { acc[im][in][0] + s0, acc[im][in][1] + s1 };
            float2 v1 = { acc[im][in][2] + s0, acc[im][in][3] + s1 };
            *(float2*)(outb + (size_t)r0 * L2n + c)       = v0;
            *(float2*)(outb + (size_t)(r0 + 8) * L2n + c) = v1;
        }
    }
}

}  // namespace

extern "C" void kernel_launch(void* const* d_in, const int* in_sizes, int n_in,
                              void* d_out, int out_size) {
    const float* ctx = nullptr;
    const float* asp = nullptr;
    const float* wu  = nullptr;
    for (int i = 0; i < n_in; i++) {
        const long sz = (long)in_sizes[i];
        if (sz == (long)Bsz * L1 * H2)       ctx = (const float*)d_in[i];
        else if (sz == (long)Bsz * L2n * H2) asp = (const float*)d_in[i];
        else if (sz == 3 * H2)               wu  = (const float*)d_in[i];
    }

    prep_kernel<<<(Bsz * L2n) / 8, 256>>>(asp, wu);

    cudaFuncSetAttribute(gemm_kernel, cudaFuncAttributeMaxDynamicSharedMemorySize,
                         SMEM_TOTAL);
    dim3 grid(L1 / 128, Bsz);
    gemm_kernel<<<grid, 256, SMEM_TOTAL>>>(ctx, (float*)d_out);
}